// round 1
// baseline (speedup 1.0000x reference)
#include <cuda_runtime.h>

#define NT   2304      // tokens
#define DIM  256       // model dim
#define KNB  289       // padded neighbors per token
#define NH   8         // heads
#define HD   32        // head dim

// scratch (allocation-free rule: device globals)
__device__ float g_x2f[NT * DIM];       // fused + layernormed x2
__device__ float g_qkv[NT * 3 * DIM];   // [n][ q(256) | k(256) | v(256) ]
__device__ float g_o[NT * DIM];         // attention output

// ---------------------------------------------------------------------------
// Kernel 1: neighborhood attention over x2 + softmax + weighted sum + LayerNorm
// one block per token, 256 threads (thread t owns dim t)
// ---------------------------------------------------------------------------
__global__ void __launch_bounds__(256)
k_neighbor(const float* __restrict__ x2, const int* __restrict__ nbi,
           const float* __restrict__ gamma, const float* __restrict__ beta)
{
    __shared__ float xs[DIM];
    __shared__ float sc[KNB];
    __shared__ int   nidx[KNB];
    __shared__ float redm[8], reds[8], r1[8], r2[8];

    const int n    = blockIdx.x;
    const int t    = threadIdx.x;
    const int warp = t >> 5, lane = t & 31;

    xs[t] = x2[n * DIM + t];
    if (t < KNB)       nidx[t]       = nbi[n * KNB + t];
    if (t + 256 < KNB) nidx[t + 256] = nbi[n * KNB + t + 256];
    __syncthreads();

    // --- scores: warp w handles neighbors w, w+8, ... ---
    const float4 xa = reinterpret_cast<const float4*>(xs)[lane];
    const float4 xb = reinterpret_cast<const float4*>(xs)[lane + 32];
    for (int k = warp; k < KNB; k += 8) {
        const float4* xr = reinterpret_cast<const float4*>(x2 + nidx[k] * DIM);
        float4 a = xr[lane];
        float4 b = xr[lane + 32];
        float dot = xa.x * a.x + xa.y * a.y + xa.z * a.z + xa.w * a.w
                  + xb.x * b.x + xb.y * b.y + xb.z * b.z + xb.w * b.w;
        #pragma unroll
        for (int o = 16; o; o >>= 1) dot += __shfl_xor_sync(0xffffffffu, dot, o);
        if (lane == 0) sc[k] = dot * 0.0625f;   // 1/sqrt(256)
    }
    __syncthreads();

    // --- softmax over 289 scores ---
    float m = sc[t];
    if (t + 256 < KNB) m = fmaxf(m, sc[t + 256]);
    #pragma unroll
    for (int o = 16; o; o >>= 1) m = fmaxf(m, __shfl_xor_sync(0xffffffffu, m, o));
    if (lane == 0) redm[warp] = m;
    __syncthreads();
    float mx = redm[0];
    #pragma unroll
    for (int w = 1; w < 8; w++) mx = fmaxf(mx, redm[w]);

    float s = 0.f;
    {
        float p = __expf(sc[t] - mx); sc[t] = p; s += p;
        if (t + 256 < KNB) {
            float p2 = __expf(sc[t + 256] - mx); sc[t + 256] = p2; s += p2;
        }
    }
    #pragma unroll
    for (int o = 16; o; o >>= 1) s += __shfl_xor_sync(0xffffffffu, s, o);
    if (lane == 0) reds[warp] = s;
    __syncthreads();
    const float tot  = reds[0] + reds[1] + reds[2] + reds[3]
                     + reds[4] + reds[5] + reds[6] + reds[7];
    const float invs = 1.f / tot;

    // --- weighted sum over neighbors: thread t accumulates dim t ---
    float acc = 0.f;
    #pragma unroll 4
    for (int k = 0; k < KNB; k++)
        acc += sc[k] * x2[nidx[k] * DIM + t];
    acc *= invs;

    // --- LayerNorm across 256 dims ---
    float v1 = acc, v2 = acc * acc;
    #pragma unroll
    for (int o = 16; o; o >>= 1) {
        v1 += __shfl_xor_sync(0xffffffffu, v1, o);
        v2 += __shfl_xor_sync(0xffffffffu, v2, o);
    }
    if (lane == 0) { r1[warp] = v1; r2[warp] = v2; }
    __syncthreads();
    float s1 = 0.f, s2 = 0.f;
    #pragma unroll
    for (int w = 0; w < 8; w++) { s1 += r1[w]; s2 += r2[w]; }
    const float mu  = s1 * (1.f / 256.f);
    const float var = s2 * (1.f / 256.f) - mu * mu;
    const float xn  = (acc - mu) * rsqrtf(var + 1e-5f);
    g_x2f[n * DIM + t] = xn * gamma[t] + beta[t];
}

// ---------------------------------------------------------------------------
// Kernels 2 & 4: C[M][Ncols] = A[M][256] @ B[Ncols][256]^T + bias
// 64x64 tiles, 256 threads, 4x4 micro-tiles, K-chunks of 16.
// mode 0: QKV — A = (col<256 ? g_x2f : Aext(x1)), C = g_qkv
// mode 1: out — A = g_o, C = Cext
// ---------------------------------------------------------------------------
__global__ void __launch_bounds__(256)
k_gemm(const float* __restrict__ Aext, const float* __restrict__ B,
       const float* __restrict__ bias, float* __restrict__ Cext,
       int Ncols, int mode)
{
    __shared__ float As[16][65];
    __shared__ float Bs[16][65];

    const int n0 = blockIdx.x * 64;
    const int m0 = blockIdx.y * 64;

    const float* A;
    float* C;
    if (mode == 0) { A = (n0 < 256) ? g_x2f : Aext; C = g_qkv; }
    else           { A = g_o;                        C = Cext;  }

    const int t  = threadIdx.x;
    const int tx = t & 15, ty = t >> 4;
    const int lr = t >> 2;            // 0..63
    const int lk = (t & 3) * 4;       // 0,4,8,12

    float acc[4][4] = {};
    for (int k0 = 0; k0 < 256; k0 += 16) {
        __syncthreads();
        float4 av = *reinterpret_cast<const float4*>(A + (m0 + lr) * 256 + k0 + lk);
        float4 bv = *reinterpret_cast<const float4*>(B + (n0 + lr) * 256 + k0 + lk);
        As[lk + 0][lr] = av.x; As[lk + 1][lr] = av.y;
        As[lk + 2][lr] = av.z; As[lk + 3][lr] = av.w;
        Bs[lk + 0][lr] = bv.x; Bs[lk + 1][lr] = bv.y;
        Bs[lk + 2][lr] = bv.z; Bs[lk + 3][lr] = bv.w;
        __syncthreads();
        #pragma unroll
        for (int kk = 0; kk < 16; kk++) {
            float a[4], b[4];
            #pragma unroll
            for (int i = 0; i < 4; i++) a[i] = As[kk][ty * 4 + i];
            #pragma unroll
            for (int j = 0; j < 4; j++) b[j] = Bs[kk][tx * 4 + j];
            #pragma unroll
            for (int i = 0; i < 4; i++)
                #pragma unroll
                for (int j = 0; j < 4; j++)
                    acc[i][j] += a[i] * b[j];
        }
    }
    #pragma unroll
    for (int i = 0; i < 4; i++) {
        const int row = m0 + ty * 4 + i;
        #pragma unroll
        for (int j = 0; j < 4; j++) {
            const int col = n0 + tx * 4 + j;
            C[row * Ncols + col] = acc[i][j] + bias[col];
        }
    }
}

// ---------------------------------------------------------------------------
// Kernel 3: 8-head flash attention, hd=32, N=2304 keys.
// Block = 128 threads = 128 query rows of one head; online softmax in regs.
// ---------------------------------------------------------------------------
__global__ void __launch_bounds__(128)
k_attn()
{
    __shared__ float Ks[64][32];
    __shared__ float Vs[64][32];

    const int h  = blockIdx.y;
    const int t  = threadIdx.x;
    const int qi = blockIdx.x * 128 + t;

    float q[32];
    {
        const float4* qp = reinterpret_cast<const float4*>(g_qkv + qi * 768 + h * 32);
        #pragma unroll
        for (int i = 0; i < 8; i++) {
            float4 v = qp[i];
            const float sc = 0.17677669529663687f;   // 1/sqrt(32)
            q[4 * i + 0] = v.x * sc; q[4 * i + 1] = v.y * sc;
            q[4 * i + 2] = v.z * sc; q[4 * i + 3] = v.w * sc;
        }
    }
    float oa[32] = {};
    float m = -1e30f, l = 0.f;

    for (int kt = 0; kt < 36; kt++) {
        __syncthreads();
        #pragma unroll
        for (int i = t; i < 64 * 8; i += 128) {     // float4 granules
            const int r = i >> 3, c4 = i & 7;
            const float* base = g_qkv + (kt * 64 + r) * 768 + h * 32 + c4 * 4;
            float4 kv = *reinterpret_cast<const float4*>(base + 256);
            float4 vv = *reinterpret_cast<const float4*>(base + 512);
            *reinterpret_cast<float4*>(&Ks[r][c4 * 4]) = kv;
            *reinterpret_cast<float4*>(&Vs[r][c4 * 4]) = vv;
        }
        __syncthreads();

        for (int ch = 0; ch < 8; ch++) {            // 8-row sub-tiles
            float s[8];
            #pragma unroll
            for (int rr = 0; rr < 8; rr++) {
                const float* kr = &Ks[ch * 8 + rr][0];
                float d = 0.f;
                #pragma unroll
                for (int c = 0; c < 32; c++) d += q[c] * kr[c];
                s[rr] = d;
            }
            float tm = m;
            #pragma unroll
            for (int rr = 0; rr < 8; rr++) tm = fmaxf(tm, s[rr]);
            const float scale = __expf(m - tm);
            m = tm;
            l *= scale;
            #pragma unroll
            for (int c = 0; c < 32; c++) oa[c] *= scale;
            #pragma unroll
            for (int rr = 0; rr < 8; rr++) {
                const float p = __expf(s[rr] - m);
                l += p;
                const float* vr = &Vs[ch * 8 + rr][0];
                #pragma unroll
                for (int c = 0; c < 32; c++) oa[c] += p * vr[c];
            }
        }
    }
    const float invl = 1.f / l;
    float4* op = reinterpret_cast<float4*>(g_o + qi * 256 + h * 32);
    #pragma unroll
    for (int i = 0; i < 8; i++) {
        float4 v;
        v.x = oa[4 * i + 0] * invl; v.y = oa[4 * i + 1] * invl;
        v.z = oa[4 * i + 2] * invl; v.w = oa[4 * i + 3] * invl;
        op[i] = v;
    }
}

// ---------------------------------------------------------------------------
extern "C" void kernel_launch(void* const* d_in, const int* in_sizes, int n_in,
                              void* d_out, int out_size)
{
    const float* x1    = (const float*)d_in[0];
    const float* x2    = (const float*)d_in[1];
    const float* gamma = (const float*)d_in[2];
    const float* beta  = (const float*)d_in[3];
    const float* wqkv  = (const float*)d_in[4];
    const float* bqkv  = (const float*)d_in[5];
    const float* wout  = (const float*)d_in[6];
    const float* bout  = (const float*)d_in[7];
    const int*   nbi   = (const int*)d_in[8];
    float* out = (float*)d_out;

    // 1) neighbor attention + layernorm -> g_x2f
    k_neighbor<<<NT, 256>>>(x2, nbi, gamma, beta);

    // 2) QKV projections -> g_qkv  (q from g_x2f, k/v from x1)
    k_gemm<<<dim3(12, 36), 256>>>(x1, wqkv, bqkv, nullptr, 768, 0);

    // 3) multi-head attention -> g_o
    k_attn<<<dim3(18, 8), 128>>>();

    // 4) output projection -> d_out
    k_gemm<<<dim3(4, 36), 256>>>(nullptr, wout, bout, out, 256, 1);
}

// round 2
// speedup vs baseline: 1.2970x; 1.2970x over previous
#include <cuda_runtime.h>

#define NT   2304      // tokens
#define DIM  256       // model dim
#define KNB  289       // padded neighbors per token
#define NH   8         // heads
#define HD   32        // head dim

// scratch (allocation-free rule: device globals)
__device__ float g_x2f[NT * DIM];       // fused + layernormed x2
__device__ float g_qkv[NT * 3 * DIM];   // [n][ q(256) | k(256) | v(256) ]
__device__ float g_o[NT * DIM];         // attention output

// ---------------------------------------------------------------------------
// Kernel 1: neighborhood attention over x2 + softmax + weighted sum + LayerNorm
// one block per token, 256 threads (thread t owns dim t)
// ---------------------------------------------------------------------------
__global__ void __launch_bounds__(256)
k_neighbor(const float* __restrict__ x2, const int* __restrict__ nbi,
           const float* __restrict__ gamma, const float* __restrict__ beta)
{
    __shared__ float xs[DIM];
    __shared__ float sc[KNB];
    __shared__ int   nidx[KNB + 7];     // pad so unroll-8 reads stay in-bounds
    __shared__ float redm[8], reds[8], r1[8], r2[8];

    const int n    = blockIdx.x;
    const int t    = threadIdx.x;
    const int warp = t >> 5, lane = t & 31;

    xs[t] = x2[n * DIM + t];
    if (t < KNB)       nidx[t]       = nbi[n * KNB + t];
    if (t + 256 < KNB) nidx[t + 256] = nbi[n * KNB + t + 256];
    if (t < 7)         nidx[KNB + t] = nbi[n * KNB];     // harmless pad
    __syncthreads();

    // --- scores: warp w handles neighbors w, w+8, ... ---
    const float4 xa = reinterpret_cast<const float4*>(xs)[lane];
    const float4 xb = reinterpret_cast<const float4*>(xs)[lane + 32];
    for (int k = warp; k < KNB; k += 8) {
        const float4* xr = reinterpret_cast<const float4*>(x2 + nidx[k] * DIM);
        float4 a = xr[lane];
        float4 b = xr[lane + 32];
        float dot = xa.x * a.x + xa.y * a.y + xa.z * a.z + xa.w * a.w
                  + xb.x * b.x + xb.y * b.y + xb.z * b.z + xb.w * b.w;
        #pragma unroll
        for (int o = 16; o; o >>= 1) dot += __shfl_xor_sync(0xffffffffu, dot, o);
        if (lane == 0) sc[k] = dot * 0.0625f;   // 1/sqrt(256)
    }
    __syncthreads();

    // --- softmax over 289 scores ---
    float m = sc[t];
    if (t + 256 < KNB) m = fmaxf(m, sc[t + 256]);
    #pragma unroll
    for (int o = 16; o; o >>= 1) m = fmaxf(m, __shfl_xor_sync(0xffffffffu, m, o));
    if (lane == 0) redm[warp] = m;
    __syncthreads();
    float mx = redm[0];
    #pragma unroll
    for (int w = 1; w < 8; w++) mx = fmaxf(mx, redm[w]);

    float s = 0.f;
    {
        float p = __expf(sc[t] - mx); sc[t] = p; s += p;
        if (t + 256 < KNB) {
            float p2 = __expf(sc[t + 256] - mx); sc[t + 256] = p2; s += p2;
        }
    }
    #pragma unroll
    for (int o = 16; o; o >>= 1) s += __shfl_xor_sync(0xffffffffu, s, o);
    if (lane == 0) reds[warp] = s;
    __syncthreads();
    const float tot  = reds[0] + reds[1] + reds[2] + reds[3]
                     + reds[4] + reds[5] + reds[6] + reds[7];
    const float invs = 1.f / tot;

    // --- weighted sum over neighbors: thread t accumulates dim t ---
    float acc = 0.f;
    {
        int k = 0;
        #pragma unroll 1
        for (; k + 8 <= KNB; k += 8) {
            float a0 = 0.f, a1 = 0.f;
            #pragma unroll
            for (int u = 0; u < 8; u += 2) {
                a0 += sc[k + u]     * x2[nidx[k + u]     * DIM + t];
                a1 += sc[k + u + 1] * x2[nidx[k + u + 1] * DIM + t];
            }
            acc += a0 + a1;
        }
        for (; k < KNB; k++)
            acc += sc[k] * x2[nidx[k] * DIM + t];
    }
    acc *= invs;

    // --- LayerNorm across 256 dims ---
    float v1 = acc, v2 = acc * acc;
    #pragma unroll
    for (int o = 16; o; o >>= 1) {
        v1 += __shfl_xor_sync(0xffffffffu, v1, o);
        v2 += __shfl_xor_sync(0xffffffffu, v2, o);
    }
    if (lane == 0) { r1[warp] = v1; r2[warp] = v2; }
    __syncthreads();
    float s1 = 0.f, s2 = 0.f;
    #pragma unroll
    for (int w = 0; w < 8; w++) { s1 += r1[w]; s2 += r2[w]; }
    const float mu  = s1 * (1.f / 256.f);
    const float var = s2 * (1.f / 256.f) - mu * mu;
    const float xn  = (acc - mu) * rsqrtf(var + 1e-5f);
    g_x2f[n * DIM + t] = xn * gamma[t] + beta[t];
}

// ---------------------------------------------------------------------------
// Kernels 2 & 4: C[M][Ncols] = A[M][256] @ B[Ncols][256]^T + bias
// 64x64 tiles, 256 threads, 4x4 micro-tiles, K-chunks of 32,
// register-prefetch double buffering (1 sync per chunk).
// mode 0: QKV — A = (col<256 ? g_x2f : Aext(x1)), C = g_qkv
// mode 1: out — A = g_o, C = Cext
// ---------------------------------------------------------------------------
__global__ void __launch_bounds__(256)
k_gemm(const float* __restrict__ Aext, const float* __restrict__ B,
       const float* __restrict__ bias, float* __restrict__ Cext,
       int Ncols, int mode)
{
    __shared__ float As[2][32][65];
    __shared__ float Bs[2][32][65];

    const int n0 = blockIdx.x * 64;
    const int m0 = blockIdx.y * 64;

    const float* A;
    float* C;
    if (mode == 0) { A = (n0 < 256) ? g_x2f : Aext; C = g_qkv; }
    else           { A = g_o;                        C = Cext;  }

    const int t  = threadIdx.x;
    const int tx = t & 15, ty = t >> 4;
    const int lr = t >> 2;            // 0..63
    const int lk = (t & 3) * 8;       // 0,8,16,24

    const float* Arow = A + (m0 + lr) * 256 + lk;
    const float* Brow = B + (n0 + lr) * 256 + lk;

    // preload chunk 0
    {
        float4 a0 = *reinterpret_cast<const float4*>(Arow);
        float4 a1 = *reinterpret_cast<const float4*>(Arow + 4);
        float4 b0 = *reinterpret_cast<const float4*>(Brow);
        float4 b1 = *reinterpret_cast<const float4*>(Brow + 4);
        As[0][lk + 0][lr] = a0.x; As[0][lk + 1][lr] = a0.y;
        As[0][lk + 2][lr] = a0.z; As[0][lk + 3][lr] = a0.w;
        As[0][lk + 4][lr] = a1.x; As[0][lk + 5][lr] = a1.y;
        As[0][lk + 6][lr] = a1.z; As[0][lk + 7][lr] = a1.w;
        Bs[0][lk + 0][lr] = b0.x; Bs[0][lk + 1][lr] = b0.y;
        Bs[0][lk + 2][lr] = b0.z; Bs[0][lk + 3][lr] = b0.w;
        Bs[0][lk + 4][lr] = b1.x; Bs[0][lk + 5][lr] = b1.y;
        Bs[0][lk + 6][lr] = b1.z; Bs[0][lk + 7][lr] = b1.w;
    }
    __syncthreads();

    float acc[4][4] = {};
    #pragma unroll
    for (int c = 0; c < 8; c++) {
        const int cur = c & 1, nxt = cur ^ 1;
        float4 a0, a1, b0, b1;
        if (c < 7) {                      // issue next-chunk global loads early
            const float* Ap = Arow + (c + 1) * 32;
            const float* Bp = Brow + (c + 1) * 32;
            a0 = *reinterpret_cast<const float4*>(Ap);
            a1 = *reinterpret_cast<const float4*>(Ap + 4);
            b0 = *reinterpret_cast<const float4*>(Bp);
            b1 = *reinterpret_cast<const float4*>(Bp + 4);
        }
        #pragma unroll
        for (int kk = 0; kk < 32; kk++) {
            float a[4], b[4];
            #pragma unroll
            for (int i = 0; i < 4; i++) a[i] = As[cur][kk][ty * 4 + i];
            #pragma unroll
            for (int j = 0; j < 4; j++) b[j] = Bs[cur][kk][tx * 4 + j];
            #pragma unroll
            for (int i = 0; i < 4; i++)
                #pragma unroll
                for (int j = 0; j < 4; j++)
                    acc[i][j] += a[i] * b[j];
        }
        if (c < 7) {
            As[nxt][lk + 0][lr] = a0.x; As[nxt][lk + 1][lr] = a0.y;
            As[nxt][lk + 2][lr] = a0.z; As[nxt][lk + 3][lr] = a0.w;
            As[nxt][lk + 4][lr] = a1.x; As[nxt][lk + 5][lr] = a1.y;
            As[nxt][lk + 6][lr] = a1.z; As[nxt][lk + 7][lr] = a1.w;
            Bs[nxt][lk + 0][lr] = b0.x; Bs[nxt][lk + 1][lr] = b0.y;
            Bs[nxt][lk + 2][lr] = b0.z; Bs[nxt][lk + 3][lr] = b0.w;
            Bs[nxt][lk + 4][lr] = b1.x; Bs[nxt][lk + 5][lr] = b1.y;
            Bs[nxt][lk + 6][lr] = b1.z; Bs[nxt][lk + 7][lr] = b1.w;
            __syncthreads();
        }
    }

    #pragma unroll
    for (int i = 0; i < 4; i++) {
        const int row = m0 + ty * 4 + i;
        #pragma unroll
        for (int j = 0; j < 4; j++) {
            const int col = n0 + tx * 4 + j;
            C[row * Ncols + col] = acc[i][j] + bias[col];
        }
    }
}

// ---------------------------------------------------------------------------
// Kernel 3: 8-head flash attention, hd=32, N=2304 keys.
// Block = 256 threads: thread pair (t, t+128) shares query row qi,
// half 0 processes even 64-key tiles, half 1 odd tiles; merge at end.
// ---------------------------------------------------------------------------
__global__ void __launch_bounds__(256)
k_attn()
{
    __shared__ float Ks[2][64][32];
    __shared__ float Vs[2][64][32];

    const int h       = blockIdx.y;
    const int t       = threadIdx.x;
    const int half    = t >> 7;          // 0: even tiles, 1: odd tiles
    const int q_local = t & 127;
    const int qi      = blockIdx.x * 128 + q_local;

    float q[32];
    {
        const float4* qp = reinterpret_cast<const float4*>(g_qkv + qi * 768 + h * 32);
        #pragma unroll
        for (int i = 0; i < 8; i++) {
            float4 v = qp[i];
            const float sc = 0.17677669529663687f;   // 1/sqrt(32)
            q[4 * i + 0] = v.x * sc; q[4 * i + 1] = v.y * sc;
            q[4 * i + 2] = v.z * sc; q[4 * i + 3] = v.w * sc;
        }
    }
    float oa[32] = {};
    float m = -1e30f, l = 0.f;

    for (int kt = 0; kt < 36; kt += 2) {          // stage 128 keys per iter
        __syncthreads();
        #pragma unroll
        for (int i = t; i < 128 * 8; i += 256) {  // float4 granules
            const int r = i >> 3, c4 = i & 7;
            const float* base = g_qkv + (kt * 64 + r) * 768 + h * 32 + c4 * 4;
            float4 kv = *reinterpret_cast<const float4*>(base + 256);
            float4 vv = *reinterpret_cast<const float4*>(base + 512);
            *reinterpret_cast<float4*>(&Ks[r >> 6][r & 63][c4 * 4]) = kv;
            *reinterpret_cast<float4*>(&Vs[r >> 6][r & 63][c4 * 4]) = vv;
        }
        __syncthreads();

        const float (*K)[32] = Ks[half];
        const float (*V)[32] = Vs[half];

        #pragma unroll 1
        for (int ch = 0; ch < 8; ch++) {          // 8-row sub-tiles
            float s[8];
            #pragma unroll
            for (int rr = 0; rr < 8; rr += 2) {   // 2 keys, 2 partials each
                const float* k0 = K[ch * 8 + rr];
                const float* k1 = K[ch * 8 + rr + 1];
                float d0 = 0.f, d1 = 0.f, e0 = 0.f, e1 = 0.f;
                #pragma unroll
                for (int c = 0; c < 32; c += 2) {
                    d0 += q[c]     * k0[c];
                    d1 += q[c + 1] * k0[c + 1];
                    e0 += q[c]     * k1[c];
                    e1 += q[c + 1] * k1[c + 1];
                }
                s[rr]     = d0 + d1;
                s[rr + 1] = e0 + e1;
            }
            float tm = m;
            #pragma unroll
            for (int rr = 0; rr < 8; rr++) tm = fmaxf(tm, s[rr]);
            const float scale = __expf(m - tm);
            m = tm;
            l *= scale;
            #pragma unroll
            for (int c = 0; c < 32; c++) oa[c] *= scale;
            #pragma unroll
            for (int rr = 0; rr < 8; rr++) {
                const float p = __expf(s[rr] - m);
                l += p;
                const float* vr = V[ch * 8 + rr];
                #pragma unroll
                for (int c = 0; c < 32; c++) oa[c] += p * vr[c];
            }
        }
    }

    // --- merge thread pairs (half 1 -> half 0) via smem scratch ---
    __syncthreads();
    float* s_ml = &Ks[0][0][0];      // 256 floats: [0:128) m1, [128:256) l1
    float* s_oa = &Vs[0][0][0];      // 128*32 floats
    if (half == 1) {
        s_ml[q_local]       = m;
        s_ml[128 + q_local] = l;
        #pragma unroll
        for (int c = 0; c < 32; c++) s_oa[q_local * 32 + c] = oa[c];
    }
    __syncthreads();
    if (half == 0) {
        const float m2 = s_ml[q_local], l2 = s_ml[128 + q_local];
        const float M  = fmaxf(m, m2);
        const float wa = __expf(m - M), wb = __expf(m2 - M);
        const float inv = 1.f / (l * wa + l2 * wb);
        float4* op = reinterpret_cast<float4*>(g_o + qi * 256 + h * 32);
        #pragma unroll
        for (int i = 0; i < 8; i++) {
            float4 v;
            v.x = (oa[4 * i + 0] * wa + s_oa[q_local * 32 + 4 * i + 0] * wb) * inv;
            v.y = (oa[4 * i + 1] * wa + s_oa[q_local * 32 + 4 * i + 1] * wb) * inv;
            v.z = (oa[4 * i + 2] * wa + s_oa[q_local * 32 + 4 * i + 2] * wb) * inv;
            v.w = (oa[4 * i + 3] * wa + s_oa[q_local * 32 + 4 * i + 3] * wb) * inv;
            op[i] = v;
        }
    }
}

// ---------------------------------------------------------------------------
extern "C" void kernel_launch(void* const* d_in, const int* in_sizes, int n_in,
                              void* d_out, int out_size)
{
    const float* x1    = (const float*)d_in[0];
    const float* x2    = (const float*)d_in[1];
    const float* gamma = (const float*)d_in[2];
    const float* beta  = (const float*)d_in[3];
    const float* wqkv  = (const float*)d_in[4];
    const float* bqkv  = (const float*)d_in[5];
    const float* wout  = (const float*)d_in[6];
    const float* bout  = (const float*)d_in[7];
    const int*   nbi   = (const int*)d_in[8];
    float* out = (float*)d_out;

    // 1) neighbor attention + layernorm -> g_x2f
    k_neighbor<<<NT, 256>>>(x2, nbi, gamma, beta);

    // 2) QKV projections -> g_qkv  (q from g_x2f, k/v from x1)
    k_gemm<<<dim3(12, 36), 256>>>(x1, wqkv, bqkv, nullptr, 768, 0);

    // 3) multi-head attention -> g_o
    k_attn<<<dim3(18, 8), 256>>>();

    // 4) output projection -> d_out
    k_gemm<<<dim3(4, 36), 256>>>(nullptr, wout, bout, out, 256, 1);
}